// round 1
// baseline (speedup 1.0000x reference)
#include <cuda_runtime.h>

// Problem constants (grid_sampler_2d backward, bilinear, zeros, align_corners=1)
#define NN 8
#define CC 256
#define HH 96
#define WW 96
#define HW (HH * WW)            // 9216
#define CPB 8                   // channels per block
#define NBLK (NN * (CC / CPB))  // 256 blocks
#define NTHR 1024
#define LPT (HW / NTHR)         // 9 output locations per thread (exact)

// align_corners=1: ix = (gx+1)*0.5*(W-1) = gx*47.5 + 47.5 ; d ix/d gx = 47.5
#define SCALE 47.5f

__global__ void zero_kernel(float4* __restrict__ out, int n4) {
    int i = blockIdx.x * blockDim.x + threadIdx.x;
    const float4 z = make_float4(0.f, 0.f, 0.f, 0.f);
    for (; i < n4; i += gridDim.x * blockDim.x) out[i] = z;
}

__global__ __launch_bounds__(NTHR, 1)
void gsb_kernel(const float* __restrict__ go,
                const float* __restrict__ inp,
                const float2* __restrict__ grd,
                float* __restrict__ gi,
                float* __restrict__ gg) {
    __shared__ float plane[HW];  // one input channel plane (36 KB)

    const int n  = blockIdx.x >> 5;          // 8 n
    const int c0 = (blockIdx.x & 31) * CPB;  // 32 channel groups of 8
    const int t  = threadIdx.x;

    // per-thread grad_grid accumulators (loc = t + k*NTHR, fixed across channels)
    float ax[LPT], ay[LPT];
#pragma unroll
    for (int k = 0; k < LPT; k++) { ax[k] = 0.f; ay[k] = 0.f; }

    const float2* gn = grd + (size_t)n * HW;

    for (int c = c0; c < c0 + CPB; ++c) {
        // cooperative load of input plane [96,96] into smem (float4, coalesced)
        const float4* src = (const float4*)(inp + ((size_t)n * CC + c) * HW);
        for (int i = t; i < HW / 4; i += NTHR) ((float4*)plane)[i] = src[i];
        __syncthreads();

        const float* gop = go + ((size_t)n * CC + c) * HW;
        float* gip       = gi + ((size_t)n * CC + c) * HW;

#pragma unroll
        for (int k = 0; k < LPT; k++) {
            const int loc = t + k * NTHR;  // < 9216 always
            const float2 g = gn[loc];
            const float ix = fmaf(g.x, SCALE, SCALE);
            const float iy = fmaf(g.y, SCALE, SCALE);
            const float x0f = floorf(ix), y0f = floorf(iy);
            const float wx1 = ix - x0f, wx0 = 1.f - wx1;
            const float wy1 = iy - y0f, wy0 = 1.f - wy1;
            const int x0 = (int)x0f, y0 = (int)y0f;
            const int x1 = x0 + 1, y1 = y0 + 1;
            const bool vx0 = (x0 >= 0) && (x0 < WW);
            const bool vx1 = (x1 >= 0) && (x1 < WW);
            const bool vy0 = (y0 >= 0) && (y0 < HH);
            const bool vy1 = (y1 >= 0) && (y1 < HH);

            // gather input corners from smem (zeros padding)
            const float v00 = (vy0 && vx0) ? plane[y0 * WW + x0] : 0.f;
            const float v01 = (vy0 && vx1) ? plane[y0 * WW + x1] : 0.f;
            const float v10 = (vy1 && vx0) ? plane[y1 * WW + x0] : 0.f;
            const float v11 = (vy1 && vx1) ? plane[y1 * WW + x1] : 0.f;

            const float gv = gop[loc];  // coalesced

            // scatter grad_input (global RED atomics)
            if (vy0 && vx0) atomicAdd(gip + y0 * WW + x0, gv * wy0 * wx0);
            if (vy0 && vx1) atomicAdd(gip + y0 * WW + x1, gv * wy0 * wx1);
            if (vy1 && vx0) atomicAdd(gip + y1 * WW + x0, gv * wy1 * wx0);
            if (vy1 && vx1) atomicAdd(gip + y1 * WW + x1, gv * wy1 * wx1);

            // grad_grid partials (d out / d ix, d out / d iy)
            ax[k] = fmaf(gv, wy0 * (v01 - v00) + wy1 * (v11 - v10), ax[k]);
            ay[k] = fmaf(gv, wx0 * (v10 - v00) + wx1 * (v11 - v01), ay[k]);
        }
        __syncthreads();  // before overwriting plane
    }

    // flush grad_grid partials (32 channel-group blocks contribute per (n,loc))
    float* ggp = gg + (size_t)n * HW * 2;
#pragma unroll
    for (int k = 0; k < LPT; k++) {
        const int loc = t + k * NTHR;
        atomicAdd(ggp + loc * 2 + 0, ax[k] * SCALE);
        atomicAdd(ggp + loc * 2 + 1, ay[k] * SCALE);
    }
}

extern "C" void kernel_launch(void* const* d_in, const int* in_sizes, int n_in,
                              void* d_out, int out_size) {
    const float*  go  = (const float*)d_in[0];   // grad_output [8,256,96,96]
    const float*  inp = (const float*)d_in[1];   // input       [8,256,96,96]
    const float2* grd = (const float2*)d_in[2];  // grid        [8,96,96,2]
    (void)in_sizes; (void)n_in; (void)out_size;

    float* out = (float*)d_out;
    float* gi  = out;                            // grad_input
    float* gg  = out + (size_t)NN * CC * HW;     // grad_grid

    const int total4 = (NN * CC * HW + NN * HW * 2) / 4;  // 4,755,456 float4
    zero_kernel<<<512, 1024>>>((float4*)out, total4);
    gsb_kernel<<<NBLK, NTHR>>>(go, inp, grd, gi, gg);
}

// round 2
// speedup vs baseline: 1.6550x; 1.6550x over previous
#include <cuda_runtime.h>

// grid_sampler_2d backward (bilinear, zeros padding, align_corners=1)
// N=8, C=256, H=W=Ho=Wo=96
#define NN 8
#define CC 256
#define HH 96
#define WW 96
#define HW (HH * WW)        // 9216
#define SCALE 47.5f         // align_corners=1: ix = gx*47.5 + 47.5

// ---- CSR scratch (built per run, reused across 256 channels) ----
// entries per n is exactly <= 9216*4 = 36864
__device__ int   g_cnt[NN * HW];            // counts, then reused as fill cursor
__device__ int   g_offs[NN * (HW + 1)];     // exclusive offsets
__device__ int2  g_ent[NN * HW * 4];        // {w as float bits, loc}
// grad_grid partials: [n][32 groups][9216][2]
#define GG_GROUPS 32
__device__ float g_part[NN * GG_GROUPS * HW * 2];

// ---------------------------------------------------------------------------
__global__ void zero_cnt_kernel() {
    int i = blockIdx.x * blockDim.x + threadIdx.x;
    if (i < NN * HW) g_cnt[i] = 0;
}

__device__ __forceinline__ void corners(float2 g, int& x0, int& y0,
                                        float& wx0, float& wx1,
                                        float& wy0, float& wy1) {
    float ix = fmaf(g.x, SCALE, SCALE);
    float iy = fmaf(g.y, SCALE, SCALE);
    float x0f = floorf(ix), y0f = floorf(iy);
    wx1 = ix - x0f; wx0 = 1.f - wx1;
    wy1 = iy - y0f; wy0 = 1.f - wy1;
    x0 = (int)x0f; y0 = (int)y0f;
}

// Pass A: count contributions per input pixel
__global__ __launch_bounds__(1024)
void count_kernel(const float2* __restrict__ grd) {
    const int n = blockIdx.x;
    const int t = threadIdx.x;
    const float2* gn = grd + (size_t)n * HW;
    int* cn = g_cnt + n * HW;
#pragma unroll
    for (int k = 0; k < 9; k++) {
        int loc = t + k * 1024;
        int x0, y0; float wx0, wx1, wy0, wy1;
        corners(gn[loc], x0, y0, wx0, wx1, wy0, wy1);
        int x1 = x0 + 1, y1 = y0 + 1;
        bool vx0 = (x0 >= 0) & (x0 < WW), vx1 = (x1 >= 0) & (x1 < WW);
        bool vy0 = (y0 >= 0) & (y0 < HH), vy1 = (y1 >= 0) & (y1 < HH);
        if (vy0 && vx0) atomicAdd(cn + y0 * WW + x0, 1);
        if (vy0 && vx1) atomicAdd(cn + y0 * WW + x1, 1);
        if (vy1 && vx0) atomicAdd(cn + y1 * WW + x0, 1);
        if (vy1 && vx1) atomicAdd(cn + y1 * WW + x1, 1);
    }
}

// Pass B: exclusive scan of 9216 counts per n (one block per n)
__global__ __launch_bounds__(1024)
void scan_kernel() {
    __shared__ int part[1024];
    const int n = blockIdx.x;
    const int t = threadIdx.x;
    int* cn = g_cnt + n * HW;
    int* on = g_offs + n * (HW + 1);
    int local[9];
    int s = 0;
#pragma unroll
    for (int j = 0; j < 9; j++) { local[j] = cn[t * 9 + j]; s += local[j]; }
    part[t] = s;
    __syncthreads();
    // Hillis-Steele inclusive scan
    for (int off = 1; off < 1024; off <<= 1) {
        int v = (t >= off) ? part[t - off] : 0;
        __syncthreads();
        part[t] += v;
        __syncthreads();
    }
    int run = part[t] - s;  // exclusive prefix for this thread's chunk
#pragma unroll
    for (int j = 0; j < 9; j++) {
        on[t * 9 + j] = run;
        cn[t * 9 + j] = run;  // cursor for fill pass
        run += local[j];
    }
    if (t == 1023) on[HW] = run;
}

// Pass C: fill CSR entries
__global__ __launch_bounds__(1024)
void fill_kernel(const float2* __restrict__ grd) {
    const int n = blockIdx.x;
    const int t = threadIdx.x;
    const float2* gn = grd + (size_t)n * HW;
    int* cur = g_cnt + n * HW;
    int2* en = g_ent + (size_t)n * HW * 4;
#pragma unroll
    for (int k = 0; k < 9; k++) {
        int loc = t + k * 1024;
        int x0, y0; float wx0, wx1, wy0, wy1;
        corners(gn[loc], x0, y0, wx0, wx1, wy0, wy1);
        int x1 = x0 + 1, y1 = y0 + 1;
        bool vx0 = (x0 >= 0) & (x0 < WW), vx1 = (x1 >= 0) & (x1 < WW);
        bool vy0 = (y0 >= 0) & (y0 < HH), vy1 = (y1 >= 0) & (y1 < HH);
        if (vy0 && vx0) { int s = atomicAdd(cur + y0 * WW + x0, 1);
            en[s] = make_int2(__float_as_int(wy0 * wx0), loc); }
        if (vy0 && vx1) { int s = atomicAdd(cur + y0 * WW + x1, 1);
            en[s] = make_int2(__float_as_int(wy0 * wx1), loc); }
        if (vy1 && vx0) { int s = atomicAdd(cur + y1 * WW + x0, 1);
            en[s] = make_int2(__float_as_int(wy1 * wx0), loc); }
        if (vy1 && vx1) { int s = atomicAdd(cur + y1 * WW + x1, 1);
            en[s] = make_int2(__float_as_int(wy1 * wx1), loc); }
    }
}

// ---------------------------------------------------------------------------
// grad_input gather: block = (n, group of 4 channels). 4 go planes in SMEM.
#define CG 4
#define PSTR 9220  // padded plane stride (words): %32==4 -> channels hit distinct banks
__global__ __launch_bounds__(1024)
void gi_kernel(const float* __restrict__ go, float* __restrict__ gi) {
    extern __shared__ float go4[];  // [CG][PSTR]
    const int n  = blockIdx.x >> 6;
    const int c0 = (blockIdx.x & 63) * CG;
    const int t  = threadIdx.x;

    // load 4 go planes (float4 coalesced)
#pragma unroll
    for (int c = 0; c < CG; c++) {
        const float4* src = (const float4*)(go + ((size_t)n * CC + c0 + c) * HW);
        float4* dst = (float4*)(go4 + c * PSTR);
        for (int i = t; i < HW / 4; i += 1024) dst[i] = src[i];
    }
    __syncthreads();

    const int* on = g_offs + n * (HW + 1);
    const int2* en = g_ent + (size_t)n * HW * 4;
    float* g0 = gi + ((size_t)n * CC + c0) * HW;

#pragma unroll
    for (int k = 0; k < 9; k++) {
        int p = t + k * 1024;
        int o0 = on[p], o1 = on[p + 1];
        float s0 = 0.f, s1 = 0.f, s2 = 0.f, s3 = 0.f;
        for (int e = o0; e < o1; e++) {
            int2 q = en[e];
            float w = __int_as_float(q.x);
            int loc = q.y;
            s0 = fmaf(w, go4[loc], s0);
            s1 = fmaf(w, go4[PSTR + loc], s1);
            s2 = fmaf(w, go4[2 * PSTR + loc], s2);
            s3 = fmaf(w, go4[3 * PSTR + loc], s3);
        }
        g0[p]          = s0;
        g0[HW + p]     = s1;
        g0[2 * HW + p] = s2;
        g0[3 * HW + p] = s3;
    }
}

// ---------------------------------------------------------------------------
// grad_grid: block = (n, group of 8 channels). Input plane in SMEM, partials out.
#define CPB 8
__global__ __launch_bounds__(1024, 2)
void gg_kernel(const float* __restrict__ go,
               const float* __restrict__ inp,
               const float2* __restrict__ grd) {
    __shared__ float plane[HW];
    const int n  = blockIdx.x >> 5;
    const int gb = blockIdx.x & 31;  // group 0..31
    const int c0 = gb * CPB;
    const int t  = threadIdx.x;

    float ax[9], ay[9];
#pragma unroll
    for (int k = 0; k < 9; k++) { ax[k] = 0.f; ay[k] = 0.f; }

    const float2* gn = grd + (size_t)n * HW;

    for (int c = c0; c < c0 + CPB; ++c) {
        const float4* src = (const float4*)(inp + ((size_t)n * CC + c) * HW);
        for (int i = t; i < HW / 4; i += 1024) ((float4*)plane)[i] = src[i];
        __syncthreads();

        const float* gop = go + ((size_t)n * CC + c) * HW;
#pragma unroll
        for (int k = 0; k < 9; k++) {
            int loc = t + k * 1024;
            int x0, y0; float wx0, wx1, wy0, wy1;
            corners(gn[loc], x0, y0, wx0, wx1, wy0, wy1);
            int x1 = x0 + 1, y1 = y0 + 1;
            bool vx0 = (x0 >= 0) & (x0 < WW), vx1 = (x1 >= 0) & (x1 < WW);
            bool vy0 = (y0 >= 0) & (y0 < HH), vy1 = (y1 >= 0) & (y1 < HH);
            float v00 = (vy0 && vx0) ? plane[y0 * WW + x0] : 0.f;
            float v01 = (vy0 && vx1) ? plane[y0 * WW + x1] : 0.f;
            float v10 = (vy1 && vx0) ? plane[y1 * WW + x0] : 0.f;
            float v11 = (vy1 && vx1) ? plane[y1 * WW + x1] : 0.f;
            float gv = gop[loc];
            ax[k] = fmaf(gv, wy0 * (v01 - v00) + wy1 * (v11 - v10), ax[k]);
            ay[k] = fmaf(gv, wx0 * (v10 - v00) + wx1 * (v11 - v01), ay[k]);
        }
        __syncthreads();
    }

    float2* pp = (float2*)(g_part + ((size_t)(n * GG_GROUPS + gb)) * HW * 2);
#pragma unroll
    for (int k = 0; k < 9; k++) {
        int loc = t + k * 1024;
        pp[loc] = make_float2(ax[k] * SCALE, ay[k] * SCALE);
    }
}

// reduce partials -> grad_grid (deterministic sum over 32 groups)
__global__ __launch_bounds__(1024)
void gg_reduce_kernel(float* __restrict__ gg) {
    int i = blockIdx.x * blockDim.x + threadIdx.x;  // over NN*HW*2
    if (i >= NN * HW * 2) return;
    int n = i / (HW * 2);
    int r = i - n * (HW * 2);
    const float* base = g_part + (size_t)n * GG_GROUPS * HW * 2 + r;
    float s = 0.f;
#pragma unroll
    for (int g = 0; g < GG_GROUPS; g++) s += base[(size_t)g * HW * 2];
    gg[i] = s;
}

// ---------------------------------------------------------------------------
extern "C" void kernel_launch(void* const* d_in, const int* in_sizes, int n_in,
                              void* d_out, int out_size) {
    const float*  go  = (const float*)d_in[0];   // grad_output [8,256,96,96]
    const float*  inp = (const float*)d_in[1];   // input       [8,256,96,96]
    const float2* grd = (const float2*)d_in[2];  // grid        [8,96,96,2]
    (void)in_sizes; (void)n_in; (void)out_size;

    float* out = (float*)d_out;
    float* gi  = out;                          // grad_input (fully overwritten)
    float* gg  = out + (size_t)NN * CC * HW;   // grad_grid  (fully overwritten)

    static int smem_set = 0;
    if (!smem_set) {
        cudaFuncSetAttribute(gi_kernel, cudaFuncAttributeMaxDynamicSharedMemorySize,
                             CG * PSTR * (int)sizeof(float));
        smem_set = 1;
    }

    zero_cnt_kernel<<<(NN * HW + 1023) / 1024, 1024>>>();
    count_kernel<<<NN, 1024>>>(grd);
    scan_kernel<<<NN, 1024>>>();
    fill_kernel<<<NN, 1024>>>(grd);
    gi_kernel<<<NN * 64, 1024, CG * PSTR * (int)sizeof(float)>>>(go, gi);
    gg_kernel<<<NN * 32, 1024>>>(go, inp, grd);
    gg_reduce_kernel<<<(NN * HW * 2 + 1023) / 1024, 1024>>>(gg);
}

// round 3
// speedup vs baseline: 2.2606x; 1.3659x over previous
#include <cuda_runtime.h>

// grid_sampler_2d backward (bilinear, zeros padding, align_corners=1)
// N=8, C=256, H=W=Ho=Wo=96
#define NN 8
#define CC 256
#define HH 96
#define WW 96
#define HW (HH * WW)        // 9216
#define SCALE 47.5f         // align_corners=1: ix = gx*47.5 + 47.5
#define K_SLOTS 8
#define OVF_CAP 65536

// ---- scratch ----
__device__ int  g_cnt[NN * HW];                 // per-pixel entry counter
__device__ int2 g_ent[NN * HW * K_SLOTS];       // {w bits, loc}, zero-padded
__device__ int  g_ovf_cnt;
__device__ int4 g_ovf[OVF_CAP];                 // {pix_global, w bits, loc, pad}
#define GG_GROUPS 32
__device__ float g_part[NN * GG_GROUPS * HW * 2];

// ---------------------------------------------------------------------------
__global__ void zero_scratch_kernel() {
    // zero g_ent (as int4) + g_cnt + ovf counter
    int i = blockIdx.x * blockDim.x + threadIdx.x;
    const int n4 = NN * HW * K_SLOTS / 2;  // int4 count for g_ent
    int4* e4 = (int4*)g_ent;
    const int4 z = make_int4(0, 0, 0, 0);
    for (int j = i; j < n4; j += gridDim.x * blockDim.x) e4[j] = z;
    for (int j = i; j < NN * HW; j += gridDim.x * blockDim.x) g_cnt[j] = 0;
    if (i == 0) g_ovf_cnt = 0;
}

__device__ __forceinline__ void corners(float2 g, int& x0, int& y0,
                                        float& wx0, float& wx1,
                                        float& wy0, float& wy1) {
    float ix = fmaf(g.x, SCALE, SCALE);
    float iy = fmaf(g.y, SCALE, SCALE);
    float x0f = floorf(ix), y0f = floorf(iy);
    wx1 = ix - x0f; wx0 = 1.f - wx1;
    wy1 = iy - y0f; wy0 = 1.f - wy1;
    x0 = (int)x0f; y0 = (int)y0f;
}

__device__ __forceinline__ void emit(int pix, float w, int loc) {
    int s = atomicAdd(&g_cnt[pix], 1);
    if (s < K_SLOTS) {
        g_ent[(size_t)pix * K_SLOTS + s] = make_int2(__float_as_int(w), loc);
    } else {
        int o = atomicAdd(&g_ovf_cnt, 1);
        if (o < OVF_CAP) g_ovf[o] = make_int4(pix, __float_as_int(w), loc, 0);
    }
}

// single-pass inverse-map build (replaces count+scan+fill)
__global__ __launch_bounds__(256)
void build_kernel(const float2* __restrict__ grd) {
    int i = blockIdx.x * blockDim.x + threadIdx.x;  // < NN*HW (= 73728)
    int n = i / HW;
    int loc = i - n * HW;
    int x0, y0; float wx0, wx1, wy0, wy1;
    corners(grd[i], x0, y0, wx0, wx1, wy0, wy1);
    int x1 = x0 + 1, y1 = y0 + 1;
    bool vx0 = (x0 >= 0) & (x0 < WW), vx1 = (x1 >= 0) & (x1 < WW);
    bool vy0 = (y0 >= 0) & (y0 < HH), vy1 = (y1 >= 0) & (y1 < HH);
    int base = n * HW;
    if (vy0 && vx0) emit(base + y0 * WW + x0, wy0 * wx0, loc);
    if (vy0 && vx1) emit(base + y0 * WW + x1, wy0 * wx1, loc);
    if (vy1 && vx0) emit(base + y1 * WW + x0, wy1 * wx0, loc);
    if (vy1 && vx1) emit(base + y1 * WW + x1, wy1 * wx1, loc);
}

// ---------------------------------------------------------------------------
// grad_input gather: block = (n, 4 channels). go planes interleaved in SMEM:
// go4[loc*4 + c] so one LDS.128 fetches all 4 channels for a loc.
#define CG 4
__global__ __launch_bounds__(1024, 1)
void gi_kernel(const float* __restrict__ go, float* __restrict__ gi) {
    extern __shared__ float go4[];  // [HW][4] interleaved, 147456 B
    const int n  = blockIdx.x >> 6;
    const int c0 = (blockIdx.x & 63) * CG;
    const int t  = threadIdx.x;

    const float* gp0 = go + ((size_t)n * CC + c0) * HW;
    // transpose-load: each thread handles locs t + k*1024; 4 coalesced LDG + 1 STS.128
#pragma unroll
    for (int k = 0; k < 9; k++) {
        int loc = t + k * 1024;
        float4 v;
        v.x = gp0[loc];
        v.y = gp0[HW + loc];
        v.z = gp0[2 * HW + loc];
        v.w = gp0[3 * HW + loc];
        *(float4*)&go4[loc * 4] = v;
    }
    __syncthreads();

    float* g0 = gi + ((size_t)n * CC + c0) * HW;
#pragma unroll
    for (int k = 0; k < 9; k++) {
        int p = t + k * 1024;
        const int4* eb = (const int4*)(g_ent + ((size_t)(n * HW + p)) * K_SLOTS);
        float s0 = 0.f, s1 = 0.f, s2 = 0.f, s3 = 0.f;
#pragma unroll
        for (int s = 0; s < K_SLOTS / 2; s++) {
            int4 q = eb[s];  // two entries {w,loc},{w,loc}
            float w0 = __int_as_float(q.x);
            float w1 = __int_as_float(q.z);
            float4 a = *(const float4*)&go4[q.y * 4];
            float4 b = *(const float4*)&go4[q.w * 4];
            s0 = fmaf(w0, a.x, s0); s1 = fmaf(w0, a.y, s1);
            s2 = fmaf(w0, a.z, s2); s3 = fmaf(w0, a.w, s3);
            s0 = fmaf(w1, b.x, s0); s1 = fmaf(w1, b.y, s1);
            s2 = fmaf(w1, b.z, s2); s3 = fmaf(w1, b.w, s3);
        }
        g0[p]          = s0;
        g0[HW + p]     = s1;
        g0[2 * HW + p] = s2;
        g0[3 * HW + p] = s3;
    }
}

// overflow entries (pixels with >K_SLOTS contributions): exact fixup
__global__ __launch_bounds__(256)
void fixup_kernel(const float* __restrict__ go, float* __restrict__ gi) {
    int cnt = g_ovf_cnt;
    if (cnt > OVF_CAP) cnt = OVF_CAP;
    int total = cnt * CC;
    for (int i = blockIdx.x * blockDim.x + threadIdx.x; i < total;
         i += gridDim.x * blockDim.x) {
        int e = i >> 8;          // / CC
        int c = i & (CC - 1);
        int4 o = g_ovf[e];
        int pix = o.x;           // n*HW + pixel
        float w = __int_as_float(o.y);
        int loc = o.z;
        int n = pix / HW;
        int p = pix - n * HW;
        size_t cb = ((size_t)n * CC + c) * HW;
        atomicAdd(&gi[cb + p], w * go[cb + loc]);
    }
}

// ---------------------------------------------------------------------------
// grad_grid: block = (n, group of 8 channels). input plane in SMEM, partials out.
#define CPB 8
__global__ __launch_bounds__(1024, 2)
void gg_kernel(const float* __restrict__ go,
               const float* __restrict__ inp,
               const float2* __restrict__ grd) {
    __shared__ float plane[HW];
    const int n  = blockIdx.x >> 5;
    const int gb = blockIdx.x & 31;
    const int c0 = gb * CPB;
    const int t  = threadIdx.x;

    float ax[9], ay[9];
#pragma unroll
    for (int k = 0; k < 9; k++) { ax[k] = 0.f; ay[k] = 0.f; }

    const float2* gn = grd + (size_t)n * HW;

    for (int c = c0; c < c0 + CPB; ++c) {
        const float4* src = (const float4*)(inp + ((size_t)n * CC + c) * HW);
        for (int i = t; i < HW / 4; i += 1024) ((float4*)plane)[i] = src[i];
        __syncthreads();

        const float* gop = go + ((size_t)n * CC + c) * HW;
#pragma unroll
        for (int k = 0; k < 9; k++) {
            int loc = t + k * 1024;
            int x0, y0; float wx0, wx1, wy0, wy1;
            corners(gn[loc], x0, y0, wx0, wx1, wy0, wy1);
            int x1 = x0 + 1, y1 = y0 + 1;
            bool vx0 = (x0 >= 0) & (x0 < WW), vx1 = (x1 >= 0) & (x1 < WW);
            bool vy0 = (y0 >= 0) & (y0 < HH), vy1 = (y1 >= 0) & (y1 < HH);
            float v00 = (vy0 && vx0) ? plane[y0 * WW + x0] : 0.f;
            float v01 = (vy0 && vx1) ? plane[y0 * WW + x1] : 0.f;
            float v10 = (vy1 && vx0) ? plane[y1 * WW + x0] : 0.f;
            float v11 = (vy1 && vx1) ? plane[y1 * WW + x1] : 0.f;
            float gv = gop[loc];
            ax[k] = fmaf(gv, wy0 * (v01 - v00) + wy1 * (v11 - v10), ax[k]);
            ay[k] = fmaf(gv, wx0 * (v10 - v00) + wx1 * (v11 - v01), ay[k]);
        }
        __syncthreads();
    }

    float2* pp = (float2*)(g_part + ((size_t)(n * GG_GROUPS + gb)) * HW * 2);
#pragma unroll
    for (int k = 0; k < 9; k++) {
        int loc = t + k * 1024;
        pp[loc] = make_float2(ax[k] * SCALE, ay[k] * SCALE);
    }
}

__global__ __launch_bounds__(1024)
void gg_reduce_kernel(float* __restrict__ gg) {
    int i = blockIdx.x * blockDim.x + threadIdx.x;  // over NN*HW*2
    if (i >= NN * HW * 2) return;
    int n = i / (HW * 2);
    int r = i - n * (HW * 2);
    const float* base = g_part + (size_t)n * GG_GROUPS * HW * 2 + r;
    float s = 0.f;
#pragma unroll
    for (int g = 0; g < GG_GROUPS; g++) s += base[(size_t)g * HW * 2];
    gg[i] = s;
}

// ---------------------------------------------------------------------------
extern "C" void kernel_launch(void* const* d_in, const int* in_sizes, int n_in,
                              void* d_out, int out_size) {
    const float*  go  = (const float*)d_in[0];   // grad_output [8,256,96,96]
    const float*  inp = (const float*)d_in[1];   // input       [8,256,96,96]
    const float2* grd = (const float2*)d_in[2];  // grid        [8,96,96,2]
    (void)in_sizes; (void)n_in; (void)out_size;

    float* out = (float*)d_out;
    float* gi  = out;                          // grad_input (fully overwritten)
    float* gg  = out + (size_t)NN * CC * HW;   // grad_grid  (fully overwritten)

    static int smem_set = 0;
    if (!smem_set) {
        cudaFuncSetAttribute(gi_kernel, cudaFuncAttributeMaxDynamicSharedMemorySize,
                             HW * CG * (int)sizeof(float));
        smem_set = 1;
    }

    zero_scratch_kernel<<<256, 1024>>>();
    build_kernel<<<NN * HW / 256, 256>>>(grd);
    gi_kernel<<<NN * 64, 1024, HW * CG * (int)sizeof(float)>>>(go, gi);
    gg_kernel<<<NN * 32, 1024>>>(go, inp, grd);
    fixup_kernel<<<256, 256>>>(go, gi);
    gg_reduce_kernel<<<(NN * HW * 2 + 1023) / 1024, 1024>>>(gg);
}

// round 4
// speedup vs baseline: 3.0128x; 1.3328x over previous
#include <cuda_runtime.h>

// grid_sampler_2d backward (bilinear, zeros padding, align_corners=1)
// N=8, C=256, H=W=Ho=Wo=96
#define NN 8
#define CC 256
#define HH 96
#define WW 96
#define HW (HH * WW)        // 9216
#define SCALE 47.5f         // align_corners=1: ix = gx*47.5 + 47.5
#define K_SLOTS 8
#define OVF_CAP 65536

// ---- scratch ----
__device__ int          g_cnt[NN * HW];             // per-pixel entry counter
__device__ unsigned int g_ent[NN * HW * K_SLOTS];   // {unorm16 w, uint16 loc}, zero-padded
__device__ int          g_ovf_cnt;
__device__ int4         g_ovf[OVF_CAP];             // {pix_global, w fp32 bits, loc, pad}
#define GG_GROUPS 32
__device__ float g_part[NN * GG_GROUPS * HW * 2];

// ---------------------------------------------------------------------------
__global__ void zero_scratch_kernel() {
    int i = blockIdx.x * blockDim.x + threadIdx.x;
    const int n4 = NN * HW * K_SLOTS / 4;  // int4 count for g_ent
    int4* e4 = (int4*)g_ent;
    const int4 z = make_int4(0, 0, 0, 0);
    for (int j = i; j < n4; j += gridDim.x * blockDim.x) e4[j] = z;
    for (int j = i; j < NN * HW; j += gridDim.x * blockDim.x) g_cnt[j] = 0;
    if (i == 0) g_ovf_cnt = 0;
}

__device__ __forceinline__ void corners(float2 g, int& x0, int& y0,
                                        float& wx0, float& wx1,
                                        float& wy0, float& wy1) {
    float ix = fmaf(g.x, SCALE, SCALE);
    float iy = fmaf(g.y, SCALE, SCALE);
    float x0f = floorf(ix), y0f = floorf(iy);
    wx1 = ix - x0f; wx0 = 1.f - wx1;
    wy1 = iy - y0f; wy0 = 1.f - wy1;
    x0 = (int)x0f; y0 = (int)y0f;
}

__device__ __forceinline__ void emit(int pix, float w, int loc) {
    int s = atomicAdd(&g_cnt[pix], 1);
    if (s < K_SLOTS) {
        unsigned int u = (unsigned int)(w * 65535.f + 0.5f);  // w in [0,1]
        g_ent[(size_t)pix * K_SLOTS + s] = (u << 16) | (unsigned int)loc;
    } else {
        int o = atomicAdd(&g_ovf_cnt, 1);
        if (o < OVF_CAP) g_ovf[o] = make_int4(pix, __float_as_int(w), loc, 0);
    }
}

__global__ __launch_bounds__(256)
void build_kernel(const float2* __restrict__ grd) {
    int i = blockIdx.x * blockDim.x + threadIdx.x;  // < NN*HW
    int n = i / HW;
    int loc = i - n * HW;
    int x0, y0; float wx0, wx1, wy0, wy1;
    corners(grd[i], x0, y0, wx0, wx1, wy0, wy1);
    int x1 = x0 + 1, y1 = y0 + 1;
    bool vx0 = (x0 >= 0) & (x0 < WW), vx1 = (x1 >= 0) & (x1 < WW);
    bool vy0 = (y0 >= 0) & (y0 < HH), vy1 = (y1 >= 0) & (y1 < HH);
    int base = n * HW;
    if (vy0 && vx0) emit(base + y0 * WW + x0, wy0 * wx0, loc);
    if (vy0 && vx1) emit(base + y0 * WW + x1, wy0 * wx1, loc);
    if (vy1 && vx0) emit(base + y1 * WW + x0, wy1 * wx0, loc);
    if (vy1 && vx1) emit(base + y1 * WW + x1, wy1 * wx1, loc);
}

// ---------------------------------------------------------------------------
// grad_input gather: block = (n, 4 channels). go interleaved: go4[loc*4+c].
#define CG 4
#define ACCE(q) { int loc_ = (int)((q) & 0xFFFFu);                         \
    float w_ = (float)((q) >> 16) * (1.f / 65535.f);                        \
    float4 a_ = *(const float4*)&go4[loc_ * 4];                             \
    s0 = fmaf(w_, a_.x, s0); s1 = fmaf(w_, a_.y, s1);                       \
    s2 = fmaf(w_, a_.z, s2); s3 = fmaf(w_, a_.w, s3); }

__global__ __launch_bounds__(1024, 1)
void gi_kernel(const float* __restrict__ go, float* __restrict__ gi) {
    extern __shared__ float go4[];  // [HW][4] interleaved, 147456 B
    const int n  = blockIdx.x >> 6;
    const int c0 = (blockIdx.x & 63) * CG;
    const int t  = threadIdx.x;

    const float* gp0 = go + ((size_t)n * CC + c0) * HW;
#pragma unroll
    for (int k = 0; k < 9; k++) {
        int loc = t + k * 1024;
        float4 v;
        v.x = gp0[loc];
        v.y = gp0[HW + loc];
        v.z = gp0[2 * HW + loc];
        v.w = gp0[3 * HW + loc];
        *(float4*)&go4[loc * 4] = v;
    }
    __syncthreads();

    float* g0 = gi + ((size_t)n * CC + c0) * HW;
#pragma unroll
    for (int k = 0; k < 9; k++) {
        int p = t + k * 1024;
        const uint4* eb = (const uint4*)(g_ent + ((size_t)(n * HW + p)) * K_SLOTS);
        uint4 qa = eb[0];
        uint4 qb = eb[1];
        float s0 = 0.f, s1 = 0.f, s2 = 0.f, s3 = 0.f;
        ACCE(qa.x) ACCE(qa.y) ACCE(qa.z) ACCE(qa.w)
        ACCE(qb.x) ACCE(qb.y) ACCE(qb.z) ACCE(qb.w)
        g0[p]          = s0;
        g0[HW + p]     = s1;
        g0[2 * HW + p] = s2;
        g0[3 * HW + p] = s3;
    }
}

// overflow entries (pixels with >K_SLOTS contributions): exact fixup
__global__ __launch_bounds__(256)
void fixup_kernel(const float* __restrict__ go, float* __restrict__ gi) {
    int cnt = g_ovf_cnt;
    if (cnt > OVF_CAP) cnt = OVF_CAP;
    int total = cnt * CC;
    for (int i = blockIdx.x * blockDim.x + threadIdx.x; i < total;
         i += gridDim.x * blockDim.x) {
        int e = i >> 8;
        int c = i & (CC - 1);
        int4 o = g_ovf[e];
        int pix = o.x;
        float w = __int_as_float(o.y);
        int loc = o.z;
        int n = pix / HW;
        int p = pix - n * HW;
        size_t cb = ((size_t)n * CC + c) * HW;
        atomicAdd(&gi[cb + p], w * go[cb + loc]);
    }
}

// ---------------------------------------------------------------------------
// grad_grid: block = (n, 8-channel group), two 4-channel subpasses.
// inp interleaved in SMEM: inp4[loc*4+c] -> one LDS.128 per corner per 4 ch.
__global__ __launch_bounds__(1024, 1)
void gg_kernel(const float* __restrict__ go,
               const float* __restrict__ inp,
               const float2* __restrict__ grd) {
    extern __shared__ float inp4[];  // [HW][4] interleaved, 147456 B
    const int n  = blockIdx.x >> 5;
    const int gb = blockIdx.x & 31;
    const int t  = threadIdx.x;

    float ax[9], ay[9];
#pragma unroll
    for (int k = 0; k < 9; k++) { ax[k] = 0.f; ay[k] = 0.f; }

    const float2* gn = grd + (size_t)n * HW;

    for (int sc = 0; sc < 2; sc++) {
        const int c0 = gb * 8 + sc * 4;
        const float* ip0 = inp + ((size_t)n * CC + c0) * HW;
#pragma unroll
        for (int k = 0; k < 9; k++) {
            int loc = t + k * 1024;
            float4 v;
            v.x = ip0[loc];
            v.y = ip0[HW + loc];
            v.z = ip0[2 * HW + loc];
            v.w = ip0[3 * HW + loc];
            *(float4*)&inp4[loc * 4] = v;
        }
        __syncthreads();

        const float* gp0 = go + ((size_t)n * CC + c0) * HW;
#pragma unroll
        for (int k = 0; k < 9; k++) {
            int loc = t + k * 1024;
            int x0, y0; float wx0, wx1, wy0, wy1;
            corners(gn[loc], x0, y0, wx0, wx1, wy0, wy1);
            int x1 = x0 + 1, y1 = y0 + 1;
            bool vx0 = (x0 >= 0) & (x0 < WW), vx1 = (x1 >= 0) & (x1 < WW);
            bool vy0 = (y0 >= 0) & (y0 < HH), vy1 = (y1 >= 0) & (y1 < HH);
            const float4 z4 = make_float4(0.f, 0.f, 0.f, 0.f);
            float4 v00 = (vy0 && vx0) ? *(const float4*)&inp4[(y0 * WW + x0) * 4] : z4;
            float4 v01 = (vy0 && vx1) ? *(const float4*)&inp4[(y0 * WW + x1) * 4] : z4;
            float4 v10 = (vy1 && vx0) ? *(const float4*)&inp4[(y1 * WW + x0) * 4] : z4;
            float4 v11 = (vy1 && vx1) ? *(const float4*)&inp4[(y1 * WW + x1) * 4] : z4;
            float g0 = gp0[loc];
            float g1 = gp0[HW + loc];
            float g2 = gp0[2 * HW + loc];
            float g3 = gp0[3 * HW + loc];
            float axk = ax[k], ayk = ay[k];
            axk = fmaf(g0, wy0 * (v01.x - v00.x) + wy1 * (v11.x - v10.x), axk);
            axk = fmaf(g1, wy0 * (v01.y - v00.y) + wy1 * (v11.y - v10.y), axk);
            axk = fmaf(g2, wy0 * (v01.z - v00.z) + wy1 * (v11.z - v10.z), axk);
            axk = fmaf(g3, wy0 * (v01.w - v00.w) + wy1 * (v11.w - v10.w), axk);
            ayk = fmaf(g0, wx0 * (v10.x - v00.x) + wx1 * (v11.x - v01.x), ayk);
            ayk = fmaf(g1, wx0 * (v10.y - v00.y) + wx1 * (v11.y - v01.y), ayk);
            ayk = fmaf(g2, wx0 * (v10.z - v00.z) + wx1 * (v11.z - v01.z), ayk);
            ayk = fmaf(g3, wx0 * (v10.w - v00.w) + wx1 * (v11.w - v01.w), ayk);
            ax[k] = axk; ay[k] = ayk;
        }
        __syncthreads();
    }

    float2* pp = (float2*)(g_part + ((size_t)(n * GG_GROUPS + gb)) * HW * 2);
#pragma unroll
    for (int k = 0; k < 9; k++) {
        int loc = t + k * 1024;
        pp[loc] = make_float2(ax[k] * SCALE, ay[k] * SCALE);
    }
}

__global__ __launch_bounds__(1024)
void gg_reduce_kernel(float* __restrict__ gg) {
    int i = blockIdx.x * blockDim.x + threadIdx.x;  // over NN*HW*2
    if (i >= NN * HW * 2) return;
    int n = i / (HW * 2);
    int r = i - n * (HW * 2);
    const float* base = g_part + (size_t)n * GG_GROUPS * HW * 2 + r;
    float s = 0.f;
#pragma unroll
    for (int g = 0; g < GG_GROUPS; g++) s += base[(size_t)g * HW * 2];
    gg[i] = s;
}

// ---------------------------------------------------------------------------
extern "C" void kernel_launch(void* const* d_in, const int* in_sizes, int n_in,
                              void* d_out, int out_size) {
    const float*  go  = (const float*)d_in[0];   // grad_output [8,256,96,96]
    const float*  inp = (const float*)d_in[1];   // input       [8,256,96,96]
    const float2* grd = (const float2*)d_in[2];  // grid        [8,96,96,2]
    (void)in_sizes; (void)n_in; (void)out_size;

    float* out = (float*)d_out;
    float* gi  = out;                          // grad_input (fully overwritten)
    float* gg  = out + (size_t)NN * CC * HW;   // grad_grid  (fully overwritten)

    static int smem_set = 0;
    if (!smem_set) {
        cudaFuncSetAttribute(gi_kernel, cudaFuncAttributeMaxDynamicSharedMemorySize,
                             HW * 4 * (int)sizeof(float));
        cudaFuncSetAttribute(gg_kernel, cudaFuncAttributeMaxDynamicSharedMemorySize,
                             HW * 4 * (int)sizeof(float));
        smem_set = 1;
    }

    zero_scratch_kernel<<<256, 1024>>>();
    build_kernel<<<NN * HW / 256, 256>>>(grd);
    gi_kernel<<<NN * 64, 1024, HW * 4 * (int)sizeof(float)>>>(go, gi);
    gg_kernel<<<NN * 32, 1024, HW * 4 * (int)sizeof(float)>>>(go, inp, grd);
    fixup_kernel<<<256, 256>>>(go, gi);
    gg_reduce_kernel<<<(NN * HW * 2 + 1023) / 1024, 1024>>>(gg);
}